// round 9
// baseline (speedup 1.0000x reference)
#include <cuda_runtime.h>
#include <cooperative_groups.h>
#include <math.h>

namespace cg = cooperative_groups;

#define EPS 1e-8f
typedef unsigned long long u64;
// B=64, S=64, I=64, O=64, N=1024, M=64, H=256, 4H=1024, P=268
// Round 9: 64 clusters x 4 CTAs x 512 threads, ONE batch per cluster, occ 2.
// Rank q owns n-quarter [256q,256q+256) of the batch's memory (64KB), h dims
// [64q,64q+64), gate cols {qb*256+64q..+64}, out cols [16q,16q+16). Ring-of-4
// halos for the circular shift; 3 cluster syncs/step with shadow work; deferred
// normalization (read pass uses unnormalized w, divided by Z post-sync).

__device__ float g_W[384 * 1024];   // rows 0..127 = Wx, 128..383 = Wh

struct __align__(16) SMem {
    float  mem[64 * 256];     // memory quarter [m][nl] (64 KB)
    float4 part[1024];        // scratch (16 KB), region-multiplexed
    float  wr[256], ww[256];  // unnormalized wp mid-step, normalized post-S45
    float  t1[256], t2[256];
    float  vh[2][384];        // [bank][ 0:64 x | 64:128 r | 128:384 h ]
    float  hcur[256];         // current-step full h
    float  h2own[64];         // own h quarter
    float  nnp[256];          // per-n memory norms
    float  c[64];
    float  gates[256];        // own cols: [qb*64 + jl]
    float  p[272];
    float  ppart[4][272];
    float2 krw[64];           // {kr[m], kw[m]}
    float  e[64], a[64];
    float  rrecv[4][64];
    float  rvec[64];
    float  scal[16];
    float  qhalo[4];          // [qr@next nl0, qr@prev nl255, qw@.., qw@..]
    float  wh_r[2], wh_w[2];  // normalized prev-w halos
    float  whp_r[2], whp_w[2];// unnormalized boundary wp from neighbors
    float2 xsum[4];           // per-quarter softmax sums
    float2 zrecv[4];          // per-quarter sharpen sums
    float2 red[16];
};

__device__ __forceinline__ float sigmoidf_(float x) { return 1.f / (1.f + expf(-x)); }
__device__ __forceinline__ float softplusf_(float x) { return fmaxf(x, 0.f) + log1pf(expf(-fabsf(x))); }

__device__ __forceinline__ u64 pk2(float a, float b) {
    u64 r; asm("mov.b64 %0, {%1, %2};" : "=l"(r) : "f"(a), "f"(b)); return r;
}
__device__ __forceinline__ float2 up2(u64 v) {
    float2 r; asm("mov.b64 {%0, %1}, %2;" : "=f"(r.x), "=f"(r.y) : "l"(v)); return r;
}
__device__ __forceinline__ void fma2(u64& d, u64 a, u64 b) {
    asm("fma.rn.f32x2 %0, %1, %2, %0;" : "+l"(d) : "l"(a), "l"(b));
}
__device__ __forceinline__ u64 fma2n(u64 a, u64 b, u64 c) {
    u64 d; asm("fma.rn.f32x2 %0, %1, %2, %3;" : "=l"(d) : "l"(a), "l"(b), "l"(c)); return d;
}
__device__ __forceinline__ u64 mul2(u64 a, u64 b) {
    u64 d; asm("mul.rn.f32x2 %0, %1, %2;" : "=l"(d) : "l"(a), "l"(b)); return d;
}
__device__ __forceinline__ u64 add2(u64 a, u64 b) {
    u64 d; asm("add.rn.f32x2 %0, %1, %2;" : "=l"(d) : "l"(a), "l"(b)); return d;
}
#define CL_ARRIVE() asm volatile("barrier.cluster.arrive.aligned;" ::: "memory")
#define CL_WAIT()   asm volatile("barrier.cluster.wait.aligned;"   ::: "memory")

// Block sum of float2 across 512 threads (16 warps); result in all threads.
__device__ __forceinline__ float2 blockReduceSum2(float2 v, float2* red) {
#pragma unroll
    for (int o = 16; o; o >>= 1) {
        v.x += __shfl_xor_sync(0xffffffffu, v.x, o);
        v.y += __shfl_xor_sync(0xffffffffu, v.y, o);
    }
    if ((threadIdx.x & 31) == 0) red[threadIdx.x >> 5] = v;
    __syncthreads();
    float2 w = red[threadIdx.x & 15];
#pragma unroll
    for (int o = 8; o; o >>= 1) {
        w.x += __shfl_xor_sync(0xffffffffu, w.x, o);
        w.y += __shfl_xor_sync(0xffffffffu, w.y, o);
    }
    return w;
}

__global__ void __launch_bounds__(512, 2) __cluster_dims__(4, 1, 1)
ntm_kernel(const float* __restrict__ x,       // (64,64,64)
           const float* __restrict__ b_lstm,  // (1024)
           const float* __restrict__ W_head,  // (256,268)
           const float* __restrict__ b_head,  // (268)
           const float* __restrict__ W_out,   // (320,64)
           const float* __restrict__ b_out,   // (64)
           float* __restrict__ out)           // (64,64,64)
{
    extern __shared__ char smraw[];
    SMem* s = (SMem*)smraw;
    cg::cluster_group cl = cg::this_cluster();

    const int rank = (int)cl.block_rank();    // 0..3 (n-quarter)
    const int b    = blockIdx.x >> 2;         // batch 0..63
    const int t    = threadIdx.x;

    SMem* PP[4];
#pragma unroll
    for (int i = 0; i < 4; ++i) PP[i] = (SMem*)cl.map_shared_rank(smraw, i);
    SMem* Pnext = PP[(rank + 1) & 3];
    SMem* Pprev = PP[(rank + 3) & 3];

    float*      partf = (float*)s->part;
    ulonglong2* partq = (ulonglong2*)s->part;
    float4*     mem4  = (float4*)s->mem;
    ulonglong2* memq  = (ulonglong2*)s->mem;

    // Hoisted out-GEMM constants: thread = (ch8, jc8); h rows [8ch8,8ch8+8), r rows {2ch8,2ch8+1}
    const int jc8 = t & 15, ch8 = t >> 4;
    const int col8 = rank * 16 + jc8;
    u64 w8a[4];
#pragma unroll
    for (int i = 0; i < 4; ++i)
        w8a[i] = pk2(W_out[(ch8 * 8 + 2 * i) * 64 + col8],
                     W_out[(ch8 * 8 + 2 * i + 1) * 64 + col8]);
    const u64 w8b = pk2(W_out[(256 + 2 * ch8) * 64 + col8],
                        W_out[(256 + 2 * ch8 + 1) * 64 + col8]);
    const float bo = (t < 16) ? b_out[rank * 16 + t] : 0.f;

    // ---- init ----
    {
        float4 iv = make_float4(0.01f, 0.01f, 0.01f, 0.01f);
#pragma unroll
        for (int i = 0; i < 8; ++i) mem4[i * 512 + t] = iv;   // 4096 float4
        if (t < 256) { float w0 = (rank == 0 && t == 0) ? 1.f : 0.f; s->wr[t] = w0; s->ww[t] = w0; }
        ((float*)s->vh)[t] = 0.f;
        if (t < 256) ((float*)s->vh)[512 + t] = 0.f;
        if (t < 64) {
            s->vh[0][t] = x[(b << 12) + t];   // step-0 x into bank 0
            s->c[t] = 0.f; s->rvec[t] = 0.f;
            s->e[t] = 0.f; s->a[t] = 0.f;     // step-0 deferred update = identity
        }
        if (t == 0) {
            float hv = (rank == 3) ? 1.f : 0.f;  // next CTA's nl0 is global n=0 iff rank==3
            s->wh_r[0] = hv; s->wh_w[0] = hv;
            s->wh_r[1] = 0.f; s->wh_w[1] = 0.f;
        }
    }
    cl.sync();

    float xpref = 0.f;

    for (int step = 0; step < 64; ++step) {
        const int prv = step & 1, cur = prv ^ 1;

        // ---- gates GEMV: own 256 cols (64 col4) x 8 K-chunks of 48 rows ----
        {
            int qi = t & 63, ch = t >> 6;
            int col4 = (qi >> 4) * 64 + rank * 16 + (qi & 15);
            const ulonglong2* gw2 = (const ulonglong2*)g_W;
            const float* vrow = s->vh[prv];
            u64 a01 = 0ull, a23 = 0ull;
            int r0 = ch * 48;
#pragma unroll 8
            for (int rr = r0; rr < r0 + 48; ++rr) {
                ulonglong2 w2 = gw2[rr * 256 + col4];
                float v = vrow[rr];
                u64 v2 = pk2(v, v);
                fma2(a01, w2.x, v2); fma2(a23, w2.y, v2);
            }
            ulonglong2 sa; sa.x = a01; sa.y = a23;
            partq[t] = sa;
        }
        __syncthreads();
        if (t < 64) {
            int col4 = (t >> 4) * 64 + rank * 16 + (t & 15);
            ulonglong2 bb = ((const ulonglong2*)b_lstm)[col4];
            u64 a01 = bb.x, a23 = bb.y;
#pragma unroll
            for (int ch = 0; ch < 8; ++ch) {
                ulonglong2 pc = partq[ch * 64 + t];
                a01 = add2(a01, pc.x); a23 = add2(a23, pc.y);
            }
            ulonglong2 g; g.x = a01; g.y = a23;
            ((ulonglong2*)s->gates)[t] = g;
        }
        __syncthreads();

        // ---- LSTM pointwise on own 64 dims; broadcast h ----
        if (t < 64) {
            float ig = s->gates[t],       fg = s->gates[64 + t],
                  gg = s->gates[128 + t], og = s->gates[192 + t];
            float cc = sigmoidf_(fg) * s->c[t] + sigmoidf_(ig) * tanhf(gg);
            s->c[t] = cc;
            float hv = sigmoidf_(og) * tanhf(cc);
            int gj = rank * 64 + t;
            s->h2own[t] = hv;
#pragma unroll
            for (int i = 0; i < 4; ++i) {
                PP[i]->vh[cur][128 + gj] = hv;
                PP[i]->hcur[gj] = hv;
            }
        }
        __syncthreads();

        // ---- head PARTIAL GEMM from own h quarter (64 rows x 268 cols) ----
        {
            int j, r0, nr;
            if (t < 268) { j = t; r0 = 0; nr = (j >= 244) ? 64 : 32; }
            else         { j = t - 268; r0 = 32; nr = 32; }
            const float* whp = W_head + (64 * rank) * 268 + j;
            u64 acc = 0ull;
            for (int k = r0; k < r0 + nr; k += 2) {
                u64 hv = *(const u64*)(s->h2own + k);
                u64 wv = pk2(whp[k * 268], whp[(k + 1) * 268]);
                fma2(acc, hv, wv);
            }
            float2 av = up2(acc);
            partf[t] = av.x + av.y;
        }
        __syncthreads();
        if (t < 268) {
            float v = partf[t] + ((t < 244) ? partf[268 + t] : 0.f);
#pragma unroll
            for (int i = 0; i < 4; ++i) PP[i]->ppart[rank][t] = v;
        }
        CL_ARRIVE();   // S1 arrive
        // ---- S1 shadow: deferred memory update (prev ww,e,a) + norm ----
        {
            int n4 = t & 63, mch = t >> 6;
            ulonglong2 ww2 = ((const ulonglong2*)s->ww)[n4];
            const u64 one2 = pk2(1.f, 1.f);
            u64 nn01 = 0ull, nn23 = 0ull;
#pragma unroll 4
            for (int mi = 0; mi < 8; ++mi) {
                int m = mch * 8 + mi;
                float em = s->e[m], am = s->a[m];
                u64 nem2 = pk2(-em, -em), am2 = pk2(am, am);
                ulonglong2 v2 = memq[m * 64 + n4];
                v2.x = fma2n(v2.x, fma2n(ww2.x, nem2, one2), mul2(ww2.x, am2));
                v2.y = fma2n(v2.y, fma2n(ww2.y, nem2, one2), mul2(ww2.y, am2));
                memq[m * 64 + n4] = v2;
                fma2(nn01, v2.x, v2.x); fma2(nn23, v2.y, v2.y);
            }
            ulonglong2 nnq; nnq.x = nn01; nnq.y = nn23;
            ((ulonglong2*)s->part)[512 + mch * 64 + n4] = nnq;   // float4 slots [512,1024)
        }
        CL_WAIT();     // S1: h + head partials everywhere
        __syncthreads();

        // ---- post-S1: p assembly + norm reduce ----
        if (t < 256) {
            float nn = 0.f;
#pragma unroll
            for (int mch = 0; mch < 8; ++mch) nn += partf[2048 + mch * 256 + t];
            s->nnp[t] = nn;
        } else {
            int j = t - 256;
            s->p[j] = s->ppart[0][j] + s->ppart[1][j] + s->ppart[2][j] + s->ppart[3][j]
                    + b_head[j];
            if (j < 12) {
                int j2 = 256 + j;
                s->p[j2] = s->ppart[0][j2] + s->ppart[1][j2] + s->ppart[2][j2]
                         + s->ppart[3][j2] + b_head[j2];
            }
        }
        __syncthreads();

        // ---- parse heads (duplicated in all 4 CTAs) ----
        if (t < 64) s->krw[t].x = tanhf(s->p[t]);
        else if (t < 128) s->krw[t - 64].y = tanhf(s->p[70 + t - 64]);
        else if (t < 192) s->e[t - 128] = sigmoidf_(s->p[140 + (t - 128)]);
        else if (t < 256) s->a[t - 192] = s->p[204 + (t - 192)];
        else if (t == 256) {
            s->scal[0] = softplusf_(s->p[64]);
            s->scal[1] = sigmoidf_(s->p[65]);
            float a0 = s->p[66], a1 = s->p[67], a2 = s->p[68];
            float mx = fmaxf(a0, fmaxf(a1, a2));
            float e0 = expf(a0 - mx), e1 = expf(a1 - mx), e2 = expf(a2 - mx);
            float sm = e0 + e1 + e2;
            s->scal[2] = e0 / sm; s->scal[3] = e1 / sm; s->scal[4] = e2 / sm;
            s->scal[5] = 1.f + softplusf_(s->p[69]);
        } else if (t == 288) {
            s->scal[8] = softplusf_(s->p[134]);
            s->scal[9] = sigmoidf_(s->p[135]);
            float a0 = s->p[136], a1 = s->p[137], a2 = s->p[138];
            float mx = fmaxf(a0, fmaxf(a1, a2));
            float e0 = expf(a0 - mx), e1 = expf(a1 - mx), e2 = expf(a2 - mx);
            float sm = e0 + e1 + e2;
            s->scal[10] = e0 / sm; s->scal[11] = e1 / sm; s->scal[12] = e2 / sm;
            s->scal[13] = 1.f + softplusf_(s->p[139]);
        }
        __syncthreads();
        if (t < 32) {
            float kv = s->krw[t].x, kv2 = s->krw[t + 32].x;
            float v = kv * kv + kv2 * kv2;
#pragma unroll
            for (int o = 16; o; o >>= 1) v += __shfl_xor_sync(0xffffffffu, v, o);
            if (t == 0) s->scal[6] = sqrtf(v);
        } else if (t < 64) {
            int l = t - 32;
            float kv = s->krw[l].y, kv2 = s->krw[l + 32].y;
            float v = kv * kv + kv2 * kv2;
#pragma unroll
            for (int o = 16; o; o >>= 1) v += __shfl_xor_sync(0xffffffffu, v, o);
            if (l == 0) s->scal[7] = sqrtf(v);
        }
        __syncthreads();

        // ---- addressing dots over own 256 n (2 m-halves of 32) ----
        const int nl = t & 255, mh = t >> 8;
        {
            u64 drw = 0ull;
            int m0 = mh * 32;
#pragma unroll 8
            for (int m = m0; m < m0 + 32; ++m) {
                float v = s->mem[m * 256 + nl];
                u64 kv = *(const u64*)(s->krw + m);
                fma2(drw, kv, pk2(v, v));
            }
            float2 d = up2(drw);
            s->part[t] = make_float4(d.x, d.y, 0.f, 0.f);
        }
        __syncthreads();
        const bool lead = (t < 256);
        float qr = 0.f, qw = 0.f, er = 0.f, ew = 0.f;
        if (lead) {
            float4 p0 = s->part[t], p1 = s->part[t + 256];
            float dr = p0.x + p1.x, dw = p0.y + p1.y;
            float nrm = sqrtf(s->nnp[nl]);
            qr = s->scal[0] * (dr / (s->scal[6] * nrm + EPS));
            qw = s->scal[8] * (dw / (s->scal[7] * nrm + EPS));
            if (nl == 0)   { Pprev->qhalo[0] = qr; Pprev->qhalo[2] = qw; }
            if (nl == 255) { Pnext->qhalo[1] = qr; Pnext->qhalo[3] = qw; }
            er = expf(qr);      // |q| <= beta (softplus-bounded): overflow-safe
            ew = expf(qw);
        }
        float2 lsum = blockReduceSum2(make_float2(er, ew), s->red);
        if (t == 0) {
#pragma unroll
            for (int i = 0; i < 4; ++i) PP[i]->xsum[rank] = lsum;
        }
        CL_ARRIVE();   // S3 arrive
        // ---- S3 shadow: out-GEMM h-part (resident weights) ----
        {
            u64 acc = 0ull;
#pragma unroll
            for (int i = 0; i < 4; ++i) {
                u64 hv = *(const u64*)(s->hcur + ch8 * 8 + 2 * i);
                fma2(acc, hv, w8a[i]);
            }
            float2 f = up2(acc);
            partf[3072 + t] = f.x + f.y;
        }
        CL_WAIT();     // S3: softmax quarter-sums + boundary q
        const float gsr = s->xsum[0].x + s->xsum[1].x + s->xsum[2].x + s->xsum[3].x;
        const float gsw = s->xsum[0].y + s->xsum[1].y + s->xsum[2].y + s->xsum[3].y;
        const float g_r = s->scal[1], g_w = s->scal[9];
        if (lead) {
            float wgr = g_r * (er / gsr) + (1.f - g_r) * s->wr[nl];
            float wgw = g_w * (ew / gsw) + (1.f - g_w) * s->ww[nl];
            s->t1[nl] = wgr;
            s->t2[nl] = wgw;
        }
        __syncthreads();
        float wpr = 0.f, wpw = 0.f;
        if (lead) {
            float t1p = (nl == 255) ? (g_r * (expf(s->qhalo[0]) / gsr) + (1.f - g_r) * s->wh_r[0]) : s->t1[nl + 1];
            float t1m = (nl == 0)   ? (g_r * (expf(s->qhalo[1]) / gsr) + (1.f - g_r) * s->wh_r[1]) : s->t1[nl - 1];
            float t2p = (nl == 255) ? (g_w * (expf(s->qhalo[2]) / gsw) + (1.f - g_w) * s->wh_w[0]) : s->t2[nl + 1];
            float t2m = (nl == 0)   ? (g_w * (expf(s->qhalo[3]) / gsw) + (1.f - g_w) * s->wh_w[1]) : s->t2[nl - 1];
            float wsr = s->scal[2]  * t1p + s->scal[3]  * s->t1[nl] + s->scal[4]  * t1m;
            float wsw = s->scal[10] * t2p + s->scal[11] * s->t2[nl] + s->scal[12] * t2m;
            wpr = (wsr > 0.f) ? expf(s->scal[5]  * logf(wsr)) : 0.f;
            wpw = (wsw > 0.f) ? expf(s->scal[13] * logf(wsw)) : 0.f;
            s->wr[nl] = wpr;      // UNNORMALIZED until post-S45
            s->ww[nl] = wpw;
            if (nl == 0)   { Pprev->whp_r[0] = wpr; Pprev->whp_w[0] = wpw; }
            if (nl == 255) { Pnext->whp_r[1] = wpr; Pnext->whp_w[1] = wpw; }
        }
        float2 lsp = blockReduceSum2(make_float2(wpr, wpw), s->red);  // bar publishes s->wr

        // ---- read pass with UNNORMALIZED wr ----
        {
            int n4 = t & 63, mch = t >> 6, wid = t >> 5;
            ulonglong2 wr2 = ((const ulonglong2*)s->wr)[n4];
#pragma unroll 4
            for (int mi = 0; mi < 8; ++mi) {
                int m = mch * 8 + mi;
                ulonglong2 v2 = memq[m * 64 + n4];
                u64 rp2 = 0ull;
                fma2(rp2, wr2.x, v2.x); fma2(rp2, wr2.y, v2.y);
                float2 rr = up2(rp2);
                float rp = rr.x + rr.y;
#pragma unroll
                for (int o = 16; o; o >>= 1) rp += __shfl_xor_sync(0xffffffffu, rp, o);
                if ((t & 31) == 0) partf[2048 + wid * 8 + mi] = rp;
            }
        }
        __syncthreads();
        if (t < 64) {
            int mch = t >> 3, mi = t & 7;
            float v = partf[2048 + (2 * mch) * 8 + mi] + partf[2048 + (2 * mch + 1) * 8 + mi];
#pragma unroll
            for (int i = 0; i < 4; ++i) PP[i]->rrecv[rank][t] = v;
        }
        if (t == 0) {
#pragma unroll
            for (int i = 0; i < 4; ++i) PP[i]->zrecv[rank] = lsp;
        }
        CL_ARRIVE();   // S45 arrive
        if (t < 64) {
            int sn = (step < 63) ? step + 1 : 63;
            xpref = x[((b << 6) + sn) * 64 + t];
        }
        CL_WAIT();     // S45: sharpen sums + r partials + boundary wp

        // ---- post-S45: normalize, assemble r, stage next inputs ----
        {
            float zr = s->zrecv[0].x + s->zrecv[1].x + s->zrecv[2].x + s->zrecv[3].x;
            float zw = s->zrecv[0].y + s->zrecv[1].y + s->zrecv[2].y + s->zrecv[3].y;
            float invZr = 1.f / (zr + EPS), invZw = 1.f / (zw + EPS);
            if (lead) { s->wr[nl] *= invZr; s->ww[nl] *= invZw; }
            if (t == 0) {
                s->wh_r[0] = s->whp_r[0] * invZr; s->wh_r[1] = s->whp_r[1] * invZr;
                s->wh_w[0] = s->whp_w[0] * invZw; s->wh_w[1] = s->whp_w[1] * invZw;
            }
            if (t < 64) {
                float rv = (s->rrecv[0][t] + s->rrecv[1][t] + s->rrecv[2][t]
                          + s->rrecv[3][t]) * invZr;
                s->rvec[t] = rv;
                s->vh[cur][64 + t] = rv;
                s->vh[cur][t] = xpref;
            }
        }
        __syncthreads();

        // ---- out: add r-part, reduce 32 chunks, write ----
        {
            u64 racc = 0ull;
            u64 rv2 = *(const u64*)(s->rvec + 2 * ch8);
            fma2(racc, rv2, w8b);
            float2 f = up2(racc);
            partf[3072 + t] += f.x + f.y;
        }
        __syncthreads();
        if (t < 128) {
            int jc = t & 15, g = t >> 4;   // 8 groups of 4 chunks
            float acc = 0.f;
#pragma unroll
            for (int k = 0; k < 4; ++k) acc += partf[3072 + (g * 4 + k) * 16 + jc];
            partf[g * 16 + jc] = acc;
        }
        __syncthreads();
        if (t < 16) {
            float acc = bo;
#pragma unroll
            for (int g = 0; g < 8; ++g) acc += partf[g * 16 + t];
            out[((b << 6) + step) * 64 + rank * 16 + t] = acc;
        }
        __syncthreads();
    }
}

extern "C" void kernel_launch(void* const* d_in, const int* in_sizes, int n_in,
                              void* d_out, int out_size) {
    const float* x      = (const float*)d_in[0];
    const float* Wx     = (const float*)d_in[1];
    const float* Wh     = (const float*)d_in[2];
    const float* b_lstm = (const float*)d_in[3];
    const float* W_head = (const float*)d_in[4];
    const float* b_head = (const float*)d_in[5];
    const float* W_out  = (const float*)d_in[6];
    const float* b_out  = (const float*)d_in[7];
    float* out = (float*)d_out;

    cudaMemcpyToSymbolAsync(g_W, Wx, 128 * 1024 * sizeof(float), 0,
                            cudaMemcpyDeviceToDevice, 0);
    cudaMemcpyToSymbolAsync(g_W, Wh, 256 * 1024 * sizeof(float),
                            128 * 1024 * sizeof(float), cudaMemcpyDeviceToDevice, 0);

    size_t smem = sizeof(SMem);
    cudaFuncSetAttribute(ntm_kernel, cudaFuncAttributeMaxDynamicSharedMemorySize, (int)smem);
    ntm_kernel<<<256, 512, smem>>>(x, b_lstm, W_head, b_head, W_out, b_out, out);
}

// round 10
// speedup vs baseline: 1.0246x; 1.0246x over previous
#include <cuda_runtime.h>
#include <cooperative_groups.h>
#include <math.h>

namespace cg = cooperative_groups;

#define EPS 1e-8f
typedef unsigned long long u64;
// B=64, S=64, I=64, O=64, N=1024, M=64, H=256, 4H=1024, P=268
// Round 10 = round-8 skeleton (4-CTA cluster, 2 batches, 1024 thr, occ 1, 3 syncs)
// + fused update/dots/norm single pass + prepacked vh float4 + duplicated head weights.

__device__ float  g_W[384 * 1024];    // rows 0..127 = Wx, 128..383 = Wh
__device__ float2 g_Wh2[256 * 268];   // W_head with each weight duplicated {w,w}

struct __align__(16) SMem {
    float  mem[64 * 512];     // own batch's memory half, [m][nl] (128 KB)
    float4 part[2048];        // scratch (32 KB), region-multiplexed
    float4 nnpd[8][128];      // norm partials from fused pass (16 KB)
    float  wr[512], ww[512];  // unnormalized wp mid-step, normalized post-S45
    float  t1[512], t2[512];
    float4 vh4[2][384];       // {vA,vA,vB,vB}: [bank][0:64 x |64:128 r |128:384 h]
    float2 h2c[256];          // current-step full h pairs {hA,hB}
    float2 h2own[64];         // own h-quarter pairs
    float  c[2][64];
    float  gates[2][256];
    float  p[272];
    float  ppart[4][272];
    float2 krw[64];           // {kr[m], kw[m]}
    float  e[2][64], a[2][64];// double-buffered write params (parse -> next-step update)
    float  rrecv[4][64];
    float2 rvec2[64];
    float  scal[16];
    float  qhalo[4];
    float  wh_r[2], wh_w[2];
    float  whp_r[2], whp_w[2];
    float  xch[4];
    float2 zrecv[4];
    float2 red[32];
};

__device__ __forceinline__ float sigmoidf_(float x) { return 1.f / (1.f + expf(-x)); }
__device__ __forceinline__ float softplusf_(float x) { return fmaxf(x, 0.f) + log1pf(expf(-fabsf(x))); }

__device__ __forceinline__ u64 pk2(float a, float b) {
    u64 r; asm("mov.b64 %0, {%1, %2};" : "=l"(r) : "f"(a), "f"(b)); return r;
}
__device__ __forceinline__ float2 up2(u64 v) {
    float2 r; asm("mov.b64 {%0, %1}, %2;" : "=f"(r.x), "=f"(r.y) : "l"(v)); return r;
}
__device__ __forceinline__ void fma2(u64& d, u64 a, u64 b) {
    asm("fma.rn.f32x2 %0, %1, %2, %0;" : "+l"(d) : "l"(a), "l"(b));
}
__device__ __forceinline__ u64 fma2n(u64 a, u64 b, u64 c) {
    u64 d; asm("fma.rn.f32x2 %0, %1, %2, %3;" : "=l"(d) : "l"(a), "l"(b), "l"(c)); return d;
}
__device__ __forceinline__ u64 mul2(u64 a, u64 b) {
    u64 d; asm("mul.rn.f32x2 %0, %1, %2;" : "=l"(d) : "l"(a), "l"(b)); return d;
}
__device__ __forceinline__ u64 add2(u64 a, u64 b) {
    u64 d; asm("add.rn.f32x2 %0, %1, %2;" : "=l"(d) : "l"(a), "l"(b)); return d;
}
#define CL_ARRIVE() asm volatile("barrier.cluster.arrive.aligned;" ::: "memory")
#define CL_WAIT()   asm volatile("barrier.cluster.wait.aligned;"   ::: "memory")

// Single-barrier block sum of a float2 across 1024 threads; result in all threads.
__device__ __forceinline__ float2 blockReduceSum2(float2 v, float2* red) {
#pragma unroll
    for (int o = 16; o; o >>= 1) {
        v.x += __shfl_xor_sync(0xffffffffu, v.x, o);
        v.y += __shfl_xor_sync(0xffffffffu, v.y, o);
    }
    if ((threadIdx.x & 31) == 0) red[threadIdx.x >> 5] = v;
    __syncthreads();
    float2 w = red[threadIdx.x & 31];
#pragma unroll
    for (int o = 16; o; o >>= 1) {
        w.x += __shfl_xor_sync(0xffffffffu, w.x, o);
        w.y += __shfl_xor_sync(0xffffffffu, w.y, o);
    }
    return w;
}

__global__ void dup_head_kernel(const float* __restrict__ W_head) {
    int i = blockIdx.x * blockDim.x + threadIdx.x;
    if (i < 256 * 268) { float w = W_head[i]; g_Wh2[i] = make_float2(w, w); }
}

__global__ void __launch_bounds__(1024, 1) __cluster_dims__(4, 1, 1)
ntm_kernel(const float* __restrict__ x,       // (64,64,64)
           const float* __restrict__ b_lstm,  // (1024)
           const float* __restrict__ b_head,  // (268)
           const float* __restrict__ W_out,   // (320,64)
           const float* __restrict__ b_out,   // (64)
           float* __restrict__ out)           // (64,64,64)
{
    extern __shared__ char smraw[];
    SMem* s = (SMem*)smraw;
    cg::cluster_group cl = cg::this_cluster();

    const int rank = (int)cl.block_rank();
    const int clid = blockIdx.x >> 2;
    const int t    = threadIdx.x;

    SMem* P0 = (SMem*)cl.map_shared_rank(smraw, 0);
    SMem* P1 = (SMem*)cl.map_shared_rank(smraw, 1);
    SMem* P2 = (SMem*)cl.map_shared_rank(smraw, 2);
    SMem* P3 = (SMem*)cl.map_shared_rank(smraw, 3);
    SMem* PP[4] = {P0, P1, P2, P3};
    SMem* pp = (SMem*)cl.map_shared_rank(smraw, rank ^ 1);   // pair peer

    float*      partf = (float*)s->part;
    float2*     part2 = (float2*)s->part;
    ulonglong2* partq = (ulonglong2*)s->part;
    float4*     mem4  = (float4*)s->mem;
    ulonglong2* memq  = (ulonglong2*)s->mem;

    const int bgA = clid * 2, bgB = clid * 2 + 1;

    // Hoisted out-GEMM constants
    const int jc8 = t & 15, ch8 = t >> 4;
    const int col8 = rank * 16 + jc8;
    float4 w8a;
    {
        int r0 = ch8 * 4;
        w8a = make_float4(W_out[(r0 + 0) * 64 + col8], W_out[(r0 + 1) * 64 + col8],
                          W_out[(r0 + 2) * 64 + col8], W_out[(r0 + 3) * 64 + col8]);
    }
    const float w8b = W_out[(256 + ch8) * 64 + col8];
    const float bo  = (t < 16) ? b_out[rank * 16 + t] : 0.f;

    // ---- init ----
    {
        float4 iv = make_float4(0.01f, 0.01f, 0.01f, 0.01f);
#pragma unroll
        for (int i = 0; i < 8; ++i) mem4[i * 1024 + t] = iv;
        if (t < 512) { float w0 = ((rank & 1) == 0 && t == 0) ? 1.f : 0.f; s->wr[t] = w0; s->ww[t] = w0; }
        if (t < 768) ((float4*)s->vh4)[t] = make_float4(0.f, 0.f, 0.f, 0.f);
        if (t < 256) s->h2c[t] = make_float2(0.f, 0.f);
        if (t < 128) ((float*)s->c)[t] = 0.f;
        if (t < 64) {
            s->rvec2[t] = make_float2(0.f, 0.f);
            s->h2own[t] = make_float2(0.f, 0.f);
            s->e[0][t] = 0.f; s->e[1][t] = 0.f;   // step-0 deferred update = identity
            s->a[0][t] = 0.f; s->a[1][t] = 0.f;
        }
        if (t < 64) {   // step-0 x, both batches duplicated
            float xa = x[(bgA << 6) * 64 + t], xb = x[(bgB << 6) * 64 + t];
            s->vh4[0][t] = make_float4(xa, xa, xb, xb);
        }
        if (t == 0) {
            float hv = (rank & 1) ? 1.f : 0.f;
            s->wh_r[0] = hv; s->wh_w[0] = hv;
            s->wh_r[1] = 0.f; s->wh_w[1] = 0.f;
        }
    }
    cl.sync();

    float2 xpref = make_float2(0.f, 0.f);

    for (int step = 0; step < 64; ++step) {
        const int prv = step & 1, cur = prv ^ 1;

        // ---- gates GEMM, own 256 cols x 2 batches, prepacked vh ----
        {
            int qi = t & 63, qb = qi >> 4, qw = qi & 15;
            int col4 = qb * 64 + rank * 16 + qw;
            int ch = t >> 6;
            const ulonglong2* gw2 = (const ulonglong2*)g_W;
            const ulonglong2* vrow = (const ulonglong2*)s->vh4[prv];
            u64 aA01 = 0ull, aA23 = 0ull, aB01 = 0ull, aB23 = 0ull;
            int r0 = ch * 24;
#pragma unroll 8
            for (int rr = r0; rr < r0 + 24; ++rr) {
                ulonglong2 w2 = gw2[rr * 256 + col4];
                ulonglong2 vv = vrow[rr];          // {vA,vA | vB,vB}
                fma2(aA01, w2.x, vv.x); fma2(aA23, w2.y, vv.x);
                fma2(aB01, w2.x, vv.y); fma2(aB23, w2.y, vv.y);
            }
            ulonglong2 sa; sa.x = aA01; sa.y = aA23;
            ulonglong2 sb; sb.x = aB01; sb.y = aB23;
            partq[t] = sa;
            partq[1024 + t] = sb;
        }
        __syncthreads();
        if (t < 128) {
            int bat = t >> 6, qi = t & 63;
            int qb = qi >> 4, qw = qi & 15;
            int col4 = qb * 64 + rank * 16 + qw;
            ulonglong2 bb = ((const ulonglong2*)b_lstm)[col4];
            u64 a01 = bb.x, a23 = bb.y;
#pragma unroll
            for (int ch = 0; ch < 16; ++ch) {
                ulonglong2 pc = partq[bat * 1024 + ch * 64 + qi];
                a01 = add2(a01, pc.x); a23 = add2(a23, pc.y);
            }
            ulonglong2 g; g.x = a01; g.y = a23;
            ((ulonglong2*)s->gates[bat])[qi] = g;
        }
        __syncthreads();

        // ---- LSTM pointwise; publish h (prepacked halves) to all 4 CTAs ----
        if (t < 128) {
            int bat = t >> 6, jl = t & 63;
            float ig = s->gates[bat][jl],       fg = s->gates[bat][64 + jl],
                  gg = s->gates[bat][128 + jl], og = s->gates[bat][192 + jl];
            float cc = sigmoidf_(fg) * s->c[bat][jl] + sigmoidf_(ig) * tanhf(gg);
            s->c[bat][jl] = cc;
            float hv = sigmoidf_(og) * tanhf(cc);
            int gj = rank * 64 + jl;
            ((float*)&s->h2own[jl])[bat] = hv;
            u64 hh = pk2(hv, hv);
#pragma unroll
            for (int i = 0; i < 4; ++i) {
                *((u64*)(&PP[i]->vh4[cur][128 + gj]) + bat) = hh;
                ((float*)&PP[i]->h2c[gj])[bat] = hv;
            }
        }
        __syncthreads();

        // ---- head PARTIAL GEMM from own h quarter, duplicated weights ----
        if (t < 536) {
            int half = t / 268, j = t - half * 268;
            const float2* whp = g_Wh2 + (64 * rank + half * 32) * 268 + j;
            u64 acc = 0ull;
#pragma unroll 8
            for (int k = 0; k < 32; ++k) {
                u64 wv = *(const u64*)(whp + k * 268);
                u64 hv = *(const u64*)(s->h2own + half * 32 + k);
                fma2(acc, hv, wv);
            }
            part2[t] = up2(acc);
        }
        __syncthreads();
        if (t < 268) {
            float2 pa = part2[t], pb = part2[t + 268];
            float vx = pa.x + pb.x, vy = pa.y + pb.y;
            P0->ppart[rank][t] = vx; P1->ppart[rank][t] = vx;
            P2->ppart[rank][t] = vy; P3->ppart[rank][t] = vy;
        }
        CL_ARRIVE();   // S1 arrive (no shadow work needed)
        CL_WAIT();     // S1: full h + head partials everywhere

        // ---- post-S1: p assembly ----
        if (t < 268) {
            s->p[t] = s->ppart[0][t] + s->ppart[1][t] + s->ppart[2][t] + s->ppart[3][t]
                    + b_head[t];
        }
        __syncthreads();

        // ---- parse heads (this step's params; e,a into slot prv) ----
        if (t < 64) s->krw[t].x = tanhf(s->p[t]);
        else if (t < 128) s->krw[t - 64].y = tanhf(s->p[70 + t - 64]);
        else if (t < 192) s->e[prv][t - 128] = sigmoidf_(s->p[140 + (t - 128)]);
        else if (t < 256) s->a[prv][t - 192] = s->p[204 + (t - 192)];
        else if (t == 256) {
            s->scal[0] = softplusf_(s->p[64]);
            s->scal[1] = sigmoidf_(s->p[65]);
            float a0 = s->p[66], a1 = s->p[67], a2 = s->p[68];
            float mx = fmaxf(a0, fmaxf(a1, a2));
            float e0 = expf(a0 - mx), e1 = expf(a1 - mx), e2 = expf(a2 - mx);
            float sm = e0 + e1 + e2;
            s->scal[2] = e0 / sm; s->scal[3] = e1 / sm; s->scal[4] = e2 / sm;
            s->scal[5] = 1.f + softplusf_(s->p[69]);
        } else if (t == 288) {
            s->scal[8] = softplusf_(s->p[134]);
            s->scal[9] = sigmoidf_(s->p[135]);
            float a0 = s->p[136], a1 = s->p[137], a2 = s->p[138];
            float mx = fmaxf(a0, fmaxf(a1, a2));
            float e0 = expf(a0 - mx), e1 = expf(a1 - mx), e2 = expf(a2 - mx);
            float sm = e0 + e1 + e2;
            s->scal[10] = e0 / sm; s->scal[11] = e1 / sm; s->scal[12] = e2 / sm;
            s->scal[13] = 1.f + softplusf_(s->p[139]);
        }
        __syncthreads();

        // ---- key norms (warps 0-1) + FUSED update(prev e,a,ww)+dots+norm pass ----
        if (t < 32) {
            float kv = s->krw[t].x, kv2 = s->krw[t + 32].x;
            float v = kv * kv + kv2 * kv2;
#pragma unroll
            for (int o = 16; o; o >>= 1) v += __shfl_xor_sync(0xffffffffu, v, o);
            if (t == 0) s->scal[6] = sqrtf(v);
        } else if (t < 64) {
            int l = t - 32;
            float kv = s->krw[l].y, kv2 = s->krw[l + 32].y;
            float v = kv * kv + kv2 * kv2;
#pragma unroll
            for (int o = 16; o; o >>= 1) v += __shfl_xor_sync(0xffffffffu, v, o);
            if (l == 0) s->scal[7] = sqrtf(v);
        }
        {
            int n4 = t & 127, mch = t >> 7;
            ulonglong2 ww2 = ((const ulonglong2*)s->ww)[n4];   // prev normalized ww
            const u64 one2 = pk2(1.f, 1.f);
            const float* eb = s->e[cur];   // prev step's parse slot
            const float* ab = s->a[cur];
            u64 acc0 = 0ull, acc1 = 0ull, acc2 = 0ull, acc3 = 0ull;   // {dr,dw} per n
            u64 nn01 = 0ull, nn23 = 0ull;
#pragma unroll
            for (int mi = 0; mi < 8; ++mi) {
                int m = mch * 8 + mi;
                float em = eb[m], am = ab[m];
                u64 kv = *(const u64*)(s->krw + m);
                u64 nem2 = pk2(-em, -em), am2 = pk2(am, am);
                ulonglong2 v2 = memq[m * 128 + n4];
                v2.x = fma2n(v2.x, fma2n(ww2.x, nem2, one2), mul2(ww2.x, am2));
                v2.y = fma2n(v2.y, fma2n(ww2.y, nem2, one2), mul2(ww2.y, am2));
                memq[m * 128 + n4] = v2;
                float2 v01 = up2(v2.x), v23 = up2(v2.y);
                fma2(acc0, kv, pk2(v01.x, v01.x));
                fma2(acc1, kv, pk2(v01.y, v01.y));
                fma2(acc2, kv, pk2(v23.x, v23.x));
                fma2(acc3, kv, pk2(v23.y, v23.y));
                fma2(nn01, v2.x, v2.x);
                fma2(nn23, v2.y, v2.y);
            }
            ulonglong2 d01; d01.x = acc0; d01.y = acc1;
            ulonglong2 d23; d23.x = acc2; d23.y = acc3;
            ((ulonglong2*)partf)[(mch * 128 + n4) * 2 + 0] = d01;   // pdq[mch*512 + n]
            ((ulonglong2*)partf)[(mch * 128 + n4) * 2 + 1] = d23;
            ulonglong2 nq; nq.x = nn01; nq.y = nn23;
            ((ulonglong2*)s->nnpd)[mch * 128 + n4] = nq;            // nnf[mch*512 + n]
        }
        __syncthreads();

        // ---- dots+norm reduce -> q, halos, exp ----
        const int nl = t & 511;
        const bool lead = (t < 512);
        float qr = 0.f, qw = 0.f, er = 0.f, ew = 0.f;
        if (lead) {
            const u64* pdq = (const u64*)partf;
            u64 d = add2(add2(add2(pdq[t],        pdq[512 + t]),
                              add2(pdq[1024 + t], pdq[1536 + t])),
                         add2(add2(pdq[2048 + t], pdq[2560 + t]),
                              add2(pdq[3072 + t], pdq[3584 + t])));
            float2 dd = up2(d);
            const float* nnf = (const float*)s->nnpd;
            float nn = ((nnf[t] + nnf[512 + t]) + (nnf[1024 + t] + nnf[1536 + t]))
                     + ((nnf[2048 + t] + nnf[2560 + t]) + (nnf[3072 + t] + nnf[3584 + t]));
            float nrm = sqrtf(nn);
            qr = s->scal[0] * (dd.x / (s->scal[6] * nrm + EPS));
            qw = s->scal[8] * (dd.y / (s->scal[7] * nrm + EPS));
            if (nl == 0)   { pp->qhalo[0] = qr; pp->qhalo[2] = qw; }
            if (nl == 511) { pp->qhalo[1] = qr; pp->qhalo[3] = qw; }
            er = expf(qr);      // |q| <= beta (softplus-bounded): overflow-safe
            ew = expf(qw);
        }
        float2 lsum = blockReduceSum2(make_float2(er, ew), s->red);
        if (t == 0) { pp->xch[0] = lsum.x; pp->xch[1] = lsum.y; }
        CL_ARRIVE();   // S3 arrive
        // ---- S3 shadow: out-GEMM h-part ----
        {
            const float* hb = (const float*)s->h2c;
            int r0 = ch8 * 4;
            u64 acc = 0ull;
            u64 h0 = *(const u64*)(hb + 2 * (r0 + 0));
            u64 h1 = *(const u64*)(hb + 2 * (r0 + 1));
            u64 h2 = *(const u64*)(hb + 2 * (r0 + 2));
            u64 h3 = *(const u64*)(hb + 2 * (r0 + 3));
            fma2(acc, h0, pk2(w8a.x, w8a.x));
            fma2(acc, h1, pk2(w8a.y, w8a.y));
            fma2(acc, h2, pk2(w8a.z, w8a.z));
            fma2(acc, h3, pk2(w8a.w, w8a.w));
            part2[3072 + t] = up2(acc);
        }
        CL_WAIT();     // S3: pair softmax sums + boundary q
        const float gsr = lsum.x + s->xch[0];
        const float gsw = lsum.y + s->xch[1];
        const float g_r = s->scal[1], g_w = s->scal[9];
        if (lead) {
            float wgr = g_r * (er / gsr) + (1.f - g_r) * s->wr[nl];
            float wgw = g_w * (ew / gsw) + (1.f - g_w) * s->ww[nl];
            s->t1[nl] = wgr;
            s->t2[nl] = wgw;
        }
        __syncthreads();
        float wpr = 0.f, wpw = 0.f;
        if (lead) {
            float t1p = (nl == 511) ? (g_r * (expf(s->qhalo[0]) / gsr) + (1.f - g_r) * s->wh_r[0]) : s->t1[nl + 1];
            float t1m = (nl == 0)   ? (g_r * (expf(s->qhalo[1]) / gsr) + (1.f - g_r) * s->wh_r[1]) : s->t1[nl - 1];
            float t2p = (nl == 511) ? (g_w * (expf(s->qhalo[2]) / gsw) + (1.f - g_w) * s->wh_w[0]) : s->t2[nl + 1];
            float t2m = (nl == 0)   ? (g_w * (expf(s->qhalo[3]) / gsw) + (1.f - g_w) * s->wh_w[1]) : s->t2[nl - 1];
            float wsr = s->scal[2]  * t1p + s->scal[3]  * s->t1[nl] + s->scal[4]  * t1m;
            float wsw = s->scal[10] * t2p + s->scal[11] * s->t2[nl] + s->scal[12] * t2m;
            wpr = (wsr > 0.f) ? expf(s->scal[5]  * logf(wsr)) : 0.f;
            wpw = (wsw > 0.f) ? expf(s->scal[13] * logf(wsw)) : 0.f;
            s->wr[nl] = wpr;      // UNNORMALIZED until post-S45
            s->ww[nl] = wpw;
            if (nl == 0)   { pp->whp_r[0] = wpr; pp->whp_w[0] = wpw; }
            if (nl == 511) { pp->whp_r[1] = wpr; pp->whp_w[1] = wpw; }
        }
        float2 lsp = blockReduceSum2(make_float2(wpr, wpw), s->red);  // bar publishes s->wr

        // ---- read pass with UNNORMALIZED wr ----
        {
            int n4 = t & 127, mch = t >> 7, wid = t >> 5;
            ulonglong2 wr2 = ((const ulonglong2*)s->wr)[n4];
#pragma unroll 4
            for (int mi = 0; mi < 8; ++mi) {
                int m = mch * 8 + mi;
                ulonglong2 v2 = memq[m * 128 + n4];
                u64 rp2 = 0ull;
                fma2(rp2, wr2.x, v2.x); fma2(rp2, wr2.y, v2.y);
                float2 rr = up2(rp2);
                float rp = rr.x + rr.y;
#pragma unroll
                for (int o = 16; o; o >>= 1) rp += __shfl_xor_sync(0xffffffffu, rp, o);
                if ((t & 31) == 0) partf[2048 + wid * 8 + mi] = rp;
            }
        }
        __syncthreads();
        if (t < 64) {
            int grp = t >> 3, mi = t & 7;
            float v = partf[2048 + (grp * 4 + 0) * 8 + mi]
                    + partf[2048 + (grp * 4 + 1) * 8 + mi]
                    + partf[2048 + (grp * 4 + 2) * 8 + mi]
                    + partf[2048 + (grp * 4 + 3) * 8 + mi];
#pragma unroll
            for (int i = 0; i < 4; ++i) PP[i]->rrecv[rank][t] = v;
        }
        if (t == 0) {
#pragma unroll
            for (int i = 0; i < 4; ++i) PP[i]->zrecv[rank] = lsp;
        }
        CL_ARRIVE();   // S45 arrive
        if (t < 64) {
            int sn = (step < 63) ? step + 1 : 63;
            xpref = make_float2(x[((bgA << 6) + sn) * 64 + t],
                                x[((bgB << 6) + sn) * 64 + t]);
        }
        CL_WAIT();     // S45: sharpen sums + r partials + boundary wp

        // ---- post-S45: normalize, assemble r, stage next inputs ----
        {
            float2 z0 = s->zrecv[0], z1 = s->zrecv[1], z2 = s->zrecv[2], z3 = s->zrecv[3];
            float invZrA = 1.f / ((z0.x + z1.x) + EPS), invZwA = 1.f / ((z0.y + z1.y) + EPS);
            float invZrB = 1.f / ((z2.x + z3.x) + EPS), invZwB = 1.f / ((z2.y + z3.y) + EPS);
            float invZr = (rank < 2) ? invZrA : invZrB;
            float invZw = (rank < 2) ? invZwA : invZwB;
            if (lead) { s->wr[nl] *= invZr; s->ww[nl] *= invZw; }
            if (t == 0) {
                s->wh_r[0] = s->whp_r[0] * invZr; s->wh_r[1] = s->whp_r[1] * invZr;
                s->wh_w[0] = s->whp_w[0] * invZw; s->wh_w[1] = s->whp_w[1] * invZw;
            }
            if (t < 64) {
                float2 rv = make_float2((s->rrecv[0][t] + s->rrecv[1][t]) * invZrA,
                                        (s->rrecv[2][t] + s->rrecv[3][t]) * invZrB);
                s->rvec2[t] = rv;
                s->vh4[cur][64 + t] = make_float4(rv.x, rv.x, rv.y, rv.y);
                s->vh4[cur][t]      = make_float4(xpref.x, xpref.x, xpref.y, xpref.y);
            }
        }
        __syncthreads();

        // ---- out: add r-part, reduce, write ----
        {
            float2 rv = s->rvec2[ch8];
            float2 pv = part2[3072 + t];
            pv.x += rv.x * w8b; pv.y += rv.y * w8b;
            part2[3072 + t] = pv;
        }
        __syncthreads();
        if (t < 128) {
            int jc = t & 15, g = t >> 4;
            float2 acc = make_float2(0.f, 0.f);
#pragma unroll
            for (int k = 0; k < 8; ++k) {
                float2 pv = part2[3072 + (g * 8 + k) * 16 + jc];
                acc.x += pv.x; acc.y += pv.y;
            }
            part2[t] = acc;
        }
        __syncthreads();
        if (t < 16) {
            float2 acc = make_float2(bo, bo);
#pragma unroll
            for (int g = 0; g < 8; ++g) {
                float2 pv = part2[g * 16 + t];
                acc.x += pv.x; acc.y += pv.y;
            }
            int col = rank * 16 + t;
            out[((bgA << 6) + step) * 64 + col] = acc.x;
            out[((bgB << 6) + step) * 64 + col] = acc.y;
        }
        __syncthreads();
    }
}

extern "C" void kernel_launch(void* const* d_in, const int* in_sizes, int n_in,
                              void* d_out, int out_size) {
    const float* x      = (const float*)d_in[0];
    const float* Wx     = (const float*)d_in[1];
    const float* Wh     = (const float*)d_in[2];
    const float* b_lstm = (const float*)d_in[3];
    const float* W_head = (const float*)d_in[4];
    const float* b_head = (const float*)d_in[5];
    const float* W_out  = (const float*)d_in[6];
    const float* b_out  = (const float*)d_in[7];
    float* out = (float*)d_out;

    cudaMemcpyToSymbolAsync(g_W, Wx, 128 * 1024 * sizeof(float), 0,
                            cudaMemcpyDeviceToDevice, 0);
    cudaMemcpyToSymbolAsync(g_W, Wh, 256 * 1024 * sizeof(float),
                            128 * 1024 * sizeof(float), cudaMemcpyDeviceToDevice, 0);
    dup_head_kernel<<<268, 256>>>(W_head);

    size_t smem = sizeof(SMem);
    cudaFuncSetAttribute(ntm_kernel, cudaFuncAttributeMaxDynamicSharedMemorySize, (int)smem);
    ntm_kernel<<<128, 1024, smem>>>(x, b_lstm, b_head, W_out, b_out, out);
}